// round 8
// baseline (speedup 1.0000x reference)
#include <cuda_runtime.h>

// GyroLoss forward — packed f32x2 quaternion tree (FFMA2), one thread per
// 16-increment group. Lo/hi packed lanes process the group's two 8-halves
// simultaneously. Scalar epilogue (qexp_full, log/huber) as in R6.
// Last-block finalize.

#define DT_F 0.01f
#define HUBER_F 0.005f
#define NPER4 2048
#define NPER5 1024
#define N0 5
#define TPB 256

typedef unsigned long long u64;

__device__ double g_sum4 = 0.0;
__device__ double g_sum5 = 0.0;
__device__ unsigned int g_count = 0u;

// ---------- packed f32x2 primitives ----------
__device__ __forceinline__ u64 pk2(float lo, float hi) {
    u64 r;
    asm("mov.b64 %0, {%1, %2};"
        : "=l"(r) : "r"(__float_as_uint(lo)), "r"(__float_as_uint(hi)));
    return r;
}
__device__ __forceinline__ void upk2(u64 p, float& lo, float& hi) {
    unsigned a, b;
    asm("mov.b64 {%0, %1}, %2;" : "=r"(a), "=r"(b) : "l"(p));
    lo = __uint_as_float(a); hi = __uint_as_float(b);
}
__device__ __forceinline__ u64 f2fma(u64 a, u64 b, u64 c) {
    u64 r;
    asm("fma.rn.f32x2 %0, %1, %2, %3;" : "=l"(r) : "l"(a), "l"(b), "l"(c));
    return r;
}
__device__ __forceinline__ u64 f2mul(u64 a, u64 b) {
    u64 r;
    asm("mul.rn.f32x2 %0, %1, %2;" : "=l"(r) : "l"(a), "l"(b));
    return r;
}
__device__ __forceinline__ u64 f2neg(u64 a) { return a ^ 0x8000000080000000ULL; }

// packed Hamilton product c = a ⊗ b (per lane), 19 packed instrs
__device__ __forceinline__ void qmul2(const u64 a[4], const u64 b[4], u64 c[4]) {
    u64 n1 = f2neg(a[1]), n2 = f2neg(a[2]), n3 = f2neg(a[3]);
    c[0] = f2fma(a[0], b[0], f2fma(n1,   b[1], f2fma(n2,   b[2], f2mul(n3,   b[3]))));
    c[1] = f2fma(a[0], b[1], f2fma(a[1], b[0], f2fma(a[2], b[3], f2mul(n3,   b[2]))));
    c[2] = f2fma(a[0], b[2], f2fma(n1,   b[3], f2fma(a[2], b[0], f2mul(a[3], b[1]))));
    c[3] = f2fma(a[0], b[3], f2fma(a[1], b[2], f2fma(n2,   b[1], f2mul(a[3], b[0]))));
}

// packed small-angle exp of DT*(x,y,z) per lane -> quaternion, 12 packed instrs
__device__ __forceinline__ void qexp2_small(float xl, float yl, float zl,
                                            float xh, float yh, float zh,
                                            u64 q[4]) {
    const u64 C1    = pk2(1.0f, 1.0f);
    const u64 CH    = pk2(0.25f * DT_F * DT_F, 0.25f * DT_F * DT_F);
    const u64 Cm05  = pk2(-0.5f, -0.5f);
    const u64 C24   = pk2(1.0f / 24.0f, 1.0f / 24.0f);
    const u64 Cm6   = pk2(-1.0f / 6.0f, -1.0f / 6.0f);
    const u64 C120  = pk2(1.0f / 120.0f, 1.0f / 120.0f);
    const u64 CHDT  = pk2(0.5f * DT_F, 0.5f * DT_F);
    u64 x = pk2(xl, xh), y = pk2(yl, yh), z = pk2(zl, zh);
    u64 rs = f2fma(x, x, f2fma(y, y, f2mul(z, z)));
    u64 hq = f2mul(rs, CH);
    q[0] = f2fma(f2fma(hq, C24, Cm05), hq, C1);
    u64 sf = f2mul(CHDT, f2fma(f2fma(hq, C120, Cm6), hq, C1));
    q[1] = f2mul(sf, x); q[2] = f2mul(sf, y); q[3] = f2mul(sf, z);
}

// ---------- scalar helpers (epilogue) ----------
__device__ __forceinline__ void qmul(const float a[4], const float b[4], float c[4]) {
    c[0] = a[0]*b[0] - a[1]*b[1] - a[2]*b[2] - a[3]*b[3];
    c[1] = a[0]*b[1] + a[1]*b[0] + a[2]*b[3] - a[3]*b[2];
    c[2] = a[0]*b[2] - a[1]*b[3] + a[2]*b[0] + a[3]*b[1];
    c[3] = a[0]*b[3] + a[1]*b[2] - a[2]*b[1] + a[3]*b[0];
}
__device__ __forceinline__ void qcmul(const float a[4], const float b[4], float c[4]) {
    c[0] = a[0]*b[0] + a[1]*b[1] + a[2]*b[2] + a[3]*b[3];
    c[1] = a[0]*b[1] - a[1]*b[0] - a[2]*b[3] + a[3]*b[2];
    c[2] = a[0]*b[2] + a[1]*b[3] - a[2]*b[0] - a[3]*b[1];
    c[3] = a[0]*b[3] - a[1]*b[2] + a[2]*b[1] - a[3]*b[0];
}
__device__ __forceinline__ void qexp_full(float x, float y, float z, float q[4]) {
    float sq = x*x + y*y + z*z;
    float a = sq * __frsqrt_rn(fmaxf(sq, 1e-16f));
    float h = 0.5f * a;
    float sh = __sinf(h), ch = __cosf(h);
    float sf = __fdividef(sh, fmaxf(a, 1e-8f));
    q[0] = ch; q[1] = sf * x; q[2] = sf * y; q[3] = sf * z;
}
__device__ __forceinline__ float fast_atan01(float x) {
    float t = x * x;
    float p = -0.0117212f;
    p = fmaf(p, t,  0.05265332f);
    p = fmaf(p, t, -0.11643287f);
    p = fmaf(p, t,  0.19354346f);
    p = fmaf(p, t, -0.33262347f);
    p = fmaf(p, t,  0.99997726f);
    return x * p;
}
__device__ __forceinline__ float huber3_qlog(const float q[4]) {
    float w = q[0], x = q[1], y = q[2], z = q[3];
    float sg = (w < 0.0f) ? -1.0f : 1.0f;
    w *= sg; x *= sg; y *= sg; z *= sg;
    float nv2 = x*x + y*y + z*z;
    float nv = nv2 * __frsqrt_rn(fmaxf(nv2, 1e-24f));
    float lo = fminf(nv, w), hi = fmaxf(nv, w);
    float at = fast_atan01(__fdividef(lo, hi));
    float th = 2.0f * ((nv <= w) ? at : (1.57079632679f - at));
    float f = __fdividef(th, fmaxf(nv, 1e-20f)) * (1.0f / HUBER_F);
    float acc = 0.0f;
#pragma unroll
    for (int t = 0; t < 3; t++) {
        float zz = f * ((t == 0) ? x : (t == 1) ? y : z);
        float az = fabsf(zz);
        acc += (az < 1.0f) ? (0.5f * zz * zz) : (az - 0.5f);
    }
    return acc;
}

// build two packed tree nodes from 4 leaves (lo = incr c..c+3, hi = incr c+8..c+11)
__device__ __forceinline__ void chunk4(const float al[12], const float ah[12],
                                       u64 Pa[4], u64 Pb[4]) {
    u64 L0[4], L1[4], L2[4], L3[4];
    qexp2_small(al[0], al[1],  al[2],  ah[0], ah[1],  ah[2],  L0);
    qexp2_small(al[3], al[4],  al[5],  ah[3], ah[4],  ah[5],  L1);
    qexp2_small(al[6], al[7],  al[8],  ah[6], ah[7],  ah[8],  L2);
    qexp2_small(al[9], al[10], al[11], ah[9], ah[10], ah[11], L3);
    qmul2(L0, L1, Pa);
    qmul2(L2, L3, Pb);
}

__global__ void __launch_bounds__(TPB, 3)
gyro_main_kernel(const float* __restrict__ xs, const float* __restrict__ hx,
                 float* __restrict__ out, int cnt4, int cnt5) {
    int g = blockIdx.x * TPB + threadIdx.x;          // group index (16 incr)
    int lane = threadIdx.x & 31;

    const float4* hp = reinterpret_cast<const float4*>(hx) + (size_t)g * 12;
    float4 xv = *reinterpret_cast<const float4*>(xs + (size_t)g * 48);

    // --- packed tree: lo lane = increments 0..7, hi lane = 8..15 ---
    u64 P0[4], P1[4], P2[4], P3[4];
    {
        float4 A0 = hp[0], A1 = hp[1], A2 = hp[2];   // incr 0..3
        float4 B0 = hp[6], B1 = hp[7], B2 = hp[8];   // incr 8..11
        float al[12] = {A0.x,A0.y,A0.z,A0.w, A1.x,A1.y,A1.z,A1.w, A2.x,A2.y,A2.z,A2.w};
        float ah[12] = {B0.x,B0.y,B0.z,B0.w, B1.x,B1.y,B1.z,B1.w, B2.x,B2.y,B2.z,B2.w};
        chunk4(al, ah, P0, P1);
    }
    {
        float4 A0 = hp[3], A1 = hp[4],  A2 = hp[5];  // incr 4..7
        float4 B0 = hp[9], B1 = hp[10], B2 = hp[11]; // incr 12..15
        float al[12] = {A0.x,A0.y,A0.z,A0.w, A1.x,A1.y,A1.z,A1.w, A2.x,A2.y,A2.z,A2.w};
        float ah[12] = {B0.x,B0.y,B0.z,B0.w, B1.x,B1.y,B1.z,B1.w, B2.x,B2.y,B2.z,B2.w};
        chunk4(al, ah, P2, P3);
    }
    u64 U0[4], U1[4], Q[4];
    qmul2(P0, P1, U0);
    qmul2(P2, P3, U1);
    qmul2(U0, U1, Q);

    // unpack: qa = incr 0..7 composed, qb = incr 8..15 composed
    float qa[4], qb[4];
#pragma unroll
    for (int k = 0; k < 4; k++) upk2(Q[k], qa[k], qb[k]);
    float q16[4];
    qmul(qa, qb, q16);

    // --- ground-truth quat ---
    float qR[4];
    qexp_full(xv.x, xv.y, xv.z, qR);

    // --- level-4 residual ---
    float rel4[4];
    qcmul(q16, qR, rel4);
    float h4 = huber3_qlog(rel4);
    int i4 = g & (NPER4 - 1);
    float s4 = (i4 >= N0) ? h4 : 0.0f;

    // --- level-5: even g combines with partner g+1 (lane+1) ---
    float qp[4], rp[4];
#pragma unroll
    for (int k = 0; k < 4; k++) {
        qp[k] = __shfl_down_sync(0xFFFFFFFFu, q16[k], 1);
        rp[k] = __shfl_down_sync(0xFFFFFFFFu, qR[k], 1);
    }
    float q32[4], r32[4], rel5[4];
    qmul(q16, qp, q32);
    qmul(qR, rp, r32);
    qcmul(q32, r32, rel5);
    float h5 = huber3_qlog(rel5);
    float s5 = 0.0f;
    if ((g & 1) == 0) {
        int j5 = (g >> 1) & (NPER5 - 1);
        if (j5 >= N0) s5 = h5;
    }

    // --- reduction ---
#pragma unroll
    for (int off = 16; off > 0; off >>= 1) {
        s4 += __shfl_down_sync(0xFFFFFFFFu, s4, off);
        s5 += __shfl_down_sync(0xFFFFFFFFu, s5, off);
    }
    __shared__ float sh4[TPB / 32];
    __shared__ float sh5[TPB / 32];
    int warp = threadIdx.x >> 5;
    if (lane == 0) { sh4[warp] = s4; sh5[warp] = s5; }
    __syncthreads();

    if (threadIdx.x == 0) {
        float b4 = 0.0f, b5 = 0.0f;
#pragma unroll
        for (int w = 0; w < TPB / 32; w++) { b4 += sh4[w]; b5 += sh5[w]; }
        atomicAdd(&g_sum4, (double)b4);
        atomicAdd(&g_sum5, (double)b5);
        __threadfence();
        unsigned int ticket = atomicAdd(&g_count, 1u);
        if (ticket == gridDim.x - 1) {
            double s4t = atomicAdd(&g_sum4, 0.0);
            double s5t = atomicAdd(&g_sum5, 0.0);
            // loss = W*HUBER^2 * (mean4 + 0.5*mean5); W*HUBER^2 = 25
            double loss = 25.0 * (s4t / (double)cnt4 + 0.5 * s5t / (double)cnt5);
            out[0] = (float)loss;
            g_sum4 = 0.0;
            g_sum5 = 0.0;
            __threadfence();
            g_count = 0u;
        }
    }
}

extern "C" void kernel_launch(void* const* d_in, const int* in_sizes, int n_in,
                              void* d_out, int out_size) {
    const float* xs = (const float*)d_in[0];
    // d_in[1] = dp, unused by forward
    const float* hx = (const float*)d_in[2];

    int total = in_sizes[2];              // N*T*3 = 6291456
    int groups = total / 48;              // 131072 groups of 16
    int nbatch = 64;
    int g4_per_batch = groups / nbatch;   // 2048
    int g5_per_batch = g4_per_batch / 2;  // 1024
    int cnt4 = nbatch * (g4_per_batch - N0) * 3;   // 392256
    int cnt5 = nbatch * (g5_per_batch - N0) * 3;   // 195648

    gyro_main_kernel<<<groups / TPB, TPB>>>(xs, hx, (float*)d_out, cnt4, cnt5);
}

// round 9
// speedup vs baseline: 1.3175x; 1.3175x over previous
#include <cuda_runtime.h>

// GyroLoss forward — quaternion formulation, R5 layout + intrinsic math.
// One thread per 8-increment half-group (262144 threads). Direct coalesced-ish
// float4 LDGs (no smem staging). Lane-pair shuffle builds the 16-group, lane-
// quad shuffle builds the level-5 pair, single converged log/huber per thread.
// Last-block finalize writes the scalar.

#define DT_F 0.01f
#define HUBER_F 0.005f
#define NPER4 2048
#define NPER5 1024
#define N0 5
#define TPB 256

__device__ double g_sum4 = 0.0;
__device__ double g_sum5 = 0.0;
__device__ unsigned int g_count = 0u;

// Hamilton product c = a ⊗ b  (R(a⊗b) = R(a)·R(b)); w at index 0.
__device__ __forceinline__ void qmul(const float a[4], const float b[4], float c[4]) {
    c[0] = a[0]*b[0] - a[1]*b[1] - a[2]*b[2] - a[3]*b[3];
    c[1] = a[0]*b[1] + a[1]*b[0] + a[2]*b[3] - a[3]*b[2];
    c[2] = a[0]*b[2] - a[1]*b[3] + a[2]*b[0] + a[3]*b[1];
    c[3] = a[0]*b[3] + a[1]*b[2] - a[2]*b[1] + a[3]*b[0];
}

// c = conj(a) ⊗ b   (relative rotation A^T B)
__device__ __forceinline__ void qcmul(const float a[4], const float b[4], float c[4]) {
    c[0] = a[0]*b[0] + a[1]*b[1] + a[2]*b[2] + a[3]*b[3];
    c[1] = a[0]*b[1] - a[1]*b[0] - a[2]*b[3] + a[3]*b[2];
    c[2] = a[0]*b[2] + a[1]*b[3] - a[2]*b[0] - a[3]*b[1];
    c[3] = a[0]*b[3] - a[1]*b[2] + a[2]*b[1] - a[3]*b[0];
}

// exp of small phi = DT*(x,y,z); (|phi|/2)^2 <= ~1e-3. Taylor err < 1e-12.
__device__ __forceinline__ void qexp_small(float x, float y, float z, float q[4]) {
    float rs = x*x + y*y + z*z;
    float hq = (0.25f * DT_F * DT_F) * rs;
    q[0] = 1.0f + hq * (-0.5f + hq * (1.0f / 24.0f));
    float sf = (0.5f * DT_F) * (1.0f + hq * (-(1.0f / 6.0f) + hq * (1.0f / 120.0f)));
    q[1] = sf * x; q[2] = sf * y; q[3] = sf * z;
}

// full-range exp (xs path): |phi| up to ~6, half-angle < ~3 -> __sinf OK
__device__ __forceinline__ void qexp_full(float x, float y, float z, float q[4]) {
    float sq = x*x + y*y + z*z;
    float a = sq * __frsqrt_rn(fmaxf(sq, 1e-16f));
    float h = 0.5f * a;
    float sh = __sinf(h), ch = __cosf(h);
    float sf = __fdividef(sh, fmaxf(a, 1e-8f));
    q[0] = ch; q[1] = sf * x; q[2] = sf * y; q[3] = sf * z;
}

// minimax atan on [0,1], abs err ~1e-6
__device__ __forceinline__ float fast_atan01(float x) {
    float t = x * x;
    float p = -0.0117212f;
    p = fmaf(p, t,  0.05265332f);
    p = fmaf(p, t, -0.11643287f);
    p = fmaf(p, t,  0.19354346f);
    p = fmaf(p, t, -0.33262347f);
    p = fmaf(p, t,  0.99997726f);
    return x * p;
}

// sum of Huber(phi_i/HUBER) for phi = so3_log of quat q (branch-free).
__device__ __forceinline__ float huber3_qlog(const float q[4]) {
    float w = q[0], x = q[1], y = q[2], z = q[3];
    float sg = (w < 0.0f) ? -1.0f : 1.0f;
    w *= sg; x *= sg; y *= sg; z *= sg;
    float nv2 = x*x + y*y + z*z;
    float nv = nv2 * __frsqrt_rn(fmaxf(nv2, 1e-24f));
    float lo = fminf(nv, w), hi = fmaxf(nv, w);
    float at = fast_atan01(__fdividef(lo, hi));
    float th = 2.0f * ((nv <= w) ? at : (1.57079632679f - at));
    float f = __fdividef(th, fmaxf(nv, 1e-20f)) * (1.0f / HUBER_F);
    float acc = 0.0f;
#pragma unroll
    for (int t = 0; t < 3; t++) {
        float zz = f * ((t == 0) ? x : (t == 1) ? y : z);
        float az = fabsf(zz);
        acc += (az < 1.0f) ? (0.5f * zz * zz) : (az - 0.5f);
    }
    return acc;
}

__global__ void __launch_bounds__(TPB)
gyro_main_kernel(const float* __restrict__ xs, const float* __restrict__ hx,
                 float* __restrict__ out, int cnt4, int cnt5) {
    int t = blockIdx.x * TPB + threadIdx.x;   // half-group (8 increments)
    int lane = threadIdx.x & 31;

    // --- load 8 increments (24 floats = 6 float4) + xs, front-batched ---
    const float4* hp = reinterpret_cast<const float4*>(hx) + (size_t)t * 6;
    float4 f0 = hp[0], f1 = hp[1], f2 = hp[2], f3 = hp[3], f4 = hp[4], f5 = hp[5];
    float4 xv = *reinterpret_cast<const float4*>(xs + (size_t)(t >> 1) * 48);

    // --- binary tree: 8 leaves -> q8 (matches reference association) ---
    float p0[4], p1[4], p2[4], p3[4];
    {
        float la[4], lb[4];
        qexp_small(f0.x, f0.y, f0.z, la);
        qexp_small(f0.w, f1.x, f1.y, lb);
        qmul(la, lb, p0);
        qexp_small(f1.z, f1.w, f2.x, la);
        qexp_small(f2.y, f2.z, f2.w, lb);
        qmul(la, lb, p1);
        qexp_small(f3.x, f3.y, f3.z, la);
        qexp_small(f3.w, f4.x, f4.y, lb);
        qmul(la, lb, p2);
        qexp_small(f4.z, f4.w, f5.x, la);
        qexp_small(f5.y, f5.z, f5.w, lb);
        qmul(la, lb, p3);
    }
    float u0[4], u1[4], q8[4];
    qmul(p0, p1, u0);
    qmul(p2, p3, u1);
    qmul(u0, u1, q8);

    // --- 16-group: even lane combines with odd partner ---
    float q16[4];
    {
        float qp[4];
#pragma unroll
        for (int k = 0; k < 4; k++)
            qp[k] = __shfl_down_sync(0xFFFFFFFFu, q8[k], 1);
        qmul(q8, qp, q16);                           // valid on even lanes
    }

    // --- ground-truth quat (pair lanes broadcast same float4) ---
    float qR[4];
    qexp_full(xv.x, xv.y, xv.z, qR);                 // valid on all lanes

    // --- level-5 operands: gather within lane quad ---
    int lb = lane & ~3;
    float q32[4], qR32[4];
    {
        float qa[4], qb[4], ra[4];
#pragma unroll
        for (int k = 0; k < 4; k++) {
            qa[k] = __shfl_sync(0xFFFFFFFFu, q16[k], lb);
            qb[k] = __shfl_sync(0xFFFFFFFFu, q16[k], lb | 2);
            ra[k] = __shfl_sync(0xFFFFFFFFu, qR[k],  lb);
        }
        qmul(qa, qb, q32);                           // used on lane ≡3
        qmul(ra, qR, qR32);                          // lane3's own qR = group 2j+1
    }

    // --- converged relative-rotation log + huber ---
    int m = t & 3;
    float relA[4], relB[4], rel[4];
    qcmul(q16, qR, relA);                            // level-4 (even lanes)
    qcmul(q32, qR32, relB);                          // level-5 (lane ≡3)
#pragma unroll
    for (int k = 0; k < 4; k++) rel[k] = (m == 3) ? relB[k] : relA[k];
    float h = huber3_qlog(rel);

    float s4 = 0.0f, s5 = 0.0f;
    if ((m & 1) == 0) {                              // lanes ≡0,2: level-4
        int i4 = (t >> 1) & (NPER4 - 1);
        if (i4 >= N0) s4 = h;
    } else if (m == 3) {                             // lane ≡3: level-5
        int j5 = (t >> 2) & (NPER5 - 1);
        if (j5 >= N0) s5 = h;
    }

    // --- reduction ---
#pragma unroll
    for (int off = 16; off > 0; off >>= 1) {
        s4 += __shfl_down_sync(0xFFFFFFFFu, s4, off);
        s5 += __shfl_down_sync(0xFFFFFFFFu, s5, off);
    }
    __shared__ float sh4[TPB / 32];
    __shared__ float sh5[TPB / 32];
    int warp = threadIdx.x >> 5;
    if (lane == 0) { sh4[warp] = s4; sh5[warp] = s5; }
    __syncthreads();

    if (threadIdx.x == 0) {
        float b4 = 0.0f, b5 = 0.0f;
#pragma unroll
        for (int w = 0; w < TPB / 32; w++) { b4 += sh4[w]; b5 += sh5[w]; }
        atomicAdd(&g_sum4, (double)b4);
        atomicAdd(&g_sum5, (double)b5);
        __threadfence();
        unsigned int ticket = atomicAdd(&g_count, 1u);
        if (ticket == gridDim.x - 1) {
            double s4t = atomicAdd(&g_sum4, 0.0);
            double s5t = atomicAdd(&g_sum5, 0.0);
            // loss = W*HUBER^2 * (mean4 + 0.5*mean5); W*HUBER^2 = 25
            double loss = 25.0 * (s4t / (double)cnt4 + 0.5 * s5t / (double)cnt5);
            out[0] = (float)loss;
            g_sum4 = 0.0;
            g_sum5 = 0.0;
            __threadfence();
            g_count = 0u;
        }
    }
}

extern "C" void kernel_launch(void* const* d_in, const int* in_sizes, int n_in,
                              void* d_out, int out_size) {
    const float* xs = (const float*)d_in[0];
    // d_in[1] = dp, unused by forward
    const float* hx = (const float*)d_in[2];

    int total = in_sizes[2];              // N*T*3 = 6291456
    int halves = total / 24;              // 262144 threads (8 increments each)
    int groups = total / 48;              // 131072
    int nbatch = 64;
    int g4_per_batch = groups / nbatch;   // 2048
    int g5_per_batch = g4_per_batch / 2;  // 1024
    int cnt4 = nbatch * (g4_per_batch - N0) * 3;   // 392256
    int cnt5 = nbatch * (g5_per_batch - N0) * 3;   // 195648

    gyro_main_kernel<<<halves / TPB, TPB>>>(xs, hx, (float*)d_out, cnt4, cnt5);
}